// round 10
// baseline (speedup 1.0000x reference)
#include <cuda_runtime.h>
#include <cuda_fp16.h>

#define NQ    20000
#define NA    100000
#define KNN   32
#define HID   128
#define E_F   16

#define KVB   1563              // (NA+63)/64  KV row-blocks of 64
#define QBL   157               // (NQ+127)/128 Q row-blocks of 128
#define KVC   270               // persistent CTAs for KV
#define QC    26                // persistent CTAs for Q
#define MLPB  157

// ---------------- scratch (static device globals; no runtime alloc) ----------
__device__ __align__(16) float  g_Qq [NQ * HID];
__device__ __align__(16) __half g_Ka [NA * HID];
__device__ __align__(16) __half g_Va [NA * HID];
__device__ __align__(16) float  g_agg[NQ * HID];

// ------------------------- fp16 MMA helpers ----------------------------------
__device__ __forceinline__ unsigned ph2(float x, float y) {
    __half2 h = __floats2half2_rn(x, y);
    return *reinterpret_cast<unsigned*>(&h);
}
__device__ __forceinline__ void mma16(float* d, unsigned a0, unsigned a1,
                                      unsigned a2, unsigned a3,
                                      unsigned b0, unsigned b1) {
    asm volatile(
        "mma.sync.aligned.m16n8k16.row.col.f32.f16.f16.f32 "
        "{%0,%1,%2,%3}, {%4,%5,%6,%7}, {%8,%9}, {%0,%1,%2,%3};"
        : "+f"(d[0]), "+f"(d[1]), "+f"(d[2]), "+f"(d[3])
        : "r"(a0), "r"(a1), "r"(a2), "r"(a3), "r"(b0), "r"(b1));
}

// Fragment storage (uint2 per (chunk,row,tig)): idx = (chunk*ROWS + row)*4 + tig
//   .x = half2{ M[row][16c+2tig],   M[row][16c+2tig+1] }
//   .y = half2{ M[row][16c+2tig+8], M[row][16c+2tig+9] }

// Conflict-free packer: matrix S [rows x stride] fp32 -> fragments at U.
__device__ __forceinline__ void pack_frags(
    const float* __restrict__ S, unsigned* U, int rowbase, int rows,
    int maxrow, int stride, int lgNC, int tid, int nthr)
{
    const int NC = 1 << lgNC;
    const int total = rows * NC * 4;
    for (int idx = tid; idx < total; idx += nthr) {
        const int tig    = idx & 3;
        const int rlo    = (idx >> 2) & 7;
        const int rest   = idx >> 5;
        const int chunk  = rest & (NC - 1);
        const int rblock = rest >> lgNC;
        const int row    = rblock * 8 + rlo;
        const int gr     = rowbase + row;
        float2 f0 = make_float2(0.f, 0.f), f1 = f0;
        if (gr < maxrow) {
            const float* p = S + (size_t)gr * stride + chunk * 16 + tig * 2;
            f0 = *(const float2*)p;
            f1 = *(const float2*)(p + 8);
        }
        uint2 v;
        v.x = ph2(f0.x, f0.y);
        v.y = ph2(f1.x, f1.y);
        ((uint2*)U)[(chunk * rows + row) * 4 + tig] = v;
    }
}

// 16x64 warp-tile GEMM over 8 k16 chunks (used by mlp_fused).
__device__ __forceinline__ void gemm_frag(const uint2* __restrict__ AF, int AR,
                                          const uint2* __restrict__ WF, int wcoff,
                                          float d[8][4], int mrow, int colh,
                                          int g, int tig) {
#pragma unroll
    for (int c = 0; c < 8; c++) {
        const uint2 aA = AF[(c * AR + mrow + g) * 4 + tig];
        const uint2 aB = AF[(c * AR + mrow + 8 + g) * 4 + tig];
#pragma unroll
        for (int nt = 0; nt < 8; nt++) {
            const int n = colh * 64 + nt * 8 + g;
            const uint2 b = WF[((wcoff + c) * 128 + n) * 4 + tig];
            mma16(d[nt], aA.x, aB.x, aA.y, aB.y, b.x, b.y);
        }
    }
}

// 32x64 warp-tile GEMM over 8 k16 chunks (0.75 LDS.64/MMA).
__device__ __forceinline__ void gemm_frag32(const uint2* __restrict__ AF, int AR,
                                            const uint2* __restrict__ WF,
                                            float d0[8][4], float d1[8][4],
                                            int mrow, int colh, int g, int tig) {
#pragma unroll
    for (int c = 0; c < 8; c++) {
        const uint2 aA0 = AF[(c * AR + mrow +      g) * 4 + tig];
        const uint2 aB0 = AF[(c * AR + mrow +  8 + g) * 4 + tig];
        const uint2 aA1 = AF[(c * AR + mrow + 16 + g) * 4 + tig];
        const uint2 aB1 = AF[(c * AR + mrow + 24 + g) * 4 + tig];
#pragma unroll
        for (int nt = 0; nt < 8; nt++) {
            const int n = colh * 64 + nt * 8 + g;
            const uint2 b = WF[(c * 128 + n) * 4 + tig];
            mma16(d0[nt], aA0.x, aB0.x, aA0.y, aB0.y, b.x, b.y);
            mma16(d1[nt], aA1.x, aB1.x, aA1.y, aB1.y, b.x, b.y);
        }
    }
}

// ---------------------------------------------------------------------------
// proj_all: 296 persistent CTAs, 256 threads, 2 CTAs/SM (reg cap 128).
// CTAs [0,KVC): KV blocks (BM=64); 8 warps = {K,V} x 2 rowgroups(32) x
// 2 colhalves, 32x64 tiles. Weights packed once; A double-buffered.
// CTAs [KVC,KVC+QC): Q blocks (BM=128); 8 warps = 4 rg x 2 colh, 32x64.
// Dyn smem 96KB: KV [Wk 32K][Wv 32K][A0 16K][A1 16K] / Q [Wq 32K][A 32K].
// ---------------------------------------------------------------------------
__global__ __launch_bounds__(256, 2) void proj_all(
    const float* __restrict__ hA, const float* __restrict__ hQ,
    const float* __restrict__ Wk, const float* __restrict__ Wv,
    const float* __restrict__ Wq,
    __half* __restrict__ Ck, __half* __restrict__ Cv, float* __restrict__ Cq)
{
    extern __shared__ unsigned U[];
    const int tid  = threadIdx.x;
    const int warp = tid >> 5;
    const int lane = tid & 31;
    const int g    = lane >> 2;
    const int tig  = lane & 3;

    if (blockIdx.x < KVC) {
        // ------------------------- KV persistent -------------------------
        pack_frags(Wk, U,        0, 128, 1 << 30, HID, 3, tid, 256);
        pack_frags(Wv, U + 8192, 0, 128, 1 << 30, HID, 3, tid, 256);

        // per-element decode for A staging: 8 elements/thread (recomputed,
        // not cached, to stay under the 128-reg cap)
        auto decode = [&](int e, int& row, int& smi, int& gof) {
            const int idx  = tid + e * 256;           // < 2048
            const int tg   = idx & 3;
            const int rlo  = (idx >> 2) & 7;
            const int rest = idx >> 5;
            const int chk  = rest & 7;
            row = (rest >> 3) * 8 + rlo;
            smi = (chk * 64 + row) * 4 + tg;
            gof = row * HID + chk * 16 + tg * 2;
        };

        const int sel  = warp >> 2;          // 0=K, 1=V
        const int mrow = ((warp >> 1) & 1) * 32;
        const int colh = warp & 1;
        __half* Cp = sel ? Cv : Ck;

        // prologue: pack block0 into buf0
        int blk = blockIdx.x;
        {
            const int brow = blk * 64;
#pragma unroll
            for (int e = 0; e < 8; e++) {
                int row, smi, gof;
                decode(e, row, smi, gof);
                uint2 v = make_uint2(0u, 0u);
                if (brow + row < NA) {
                    const float* p = hA + (size_t)brow * HID + gof;
                    const float2 f0 = *(const float2*)p;
                    const float2 f1 = *(const float2*)(p + 8);
                    v.x = ph2(f0.x, f0.y);
                    v.y = ph2(f1.x, f1.y);
                }
                ((uint2*)(U + 16384))[smi] = v;
            }
        }
        __syncthreads();

        int cur = 0;
        while (blk < KVB) {
            const int nxt = blk + KVC;
            // stage next block's A in registers (overlaps with MMA below)
            uint2 stg[8];
            if (nxt < KVB) {
                const int brow = nxt * 64;
#pragma unroll
                for (int e = 0; e < 8; e++) {
                    int row, smi, gof;
                    decode(e, row, smi, gof);
                    stg[e] = make_uint2(0u, 0u);
                    if (brow + row < NA) {
                        const float* p = hA + (size_t)brow * HID + gof;
                        const float2 f0 = *(const float2*)p;
                        const float2 f1 = *(const float2*)(p + 8);
                        stg[e].x = ph2(f0.x, f0.y);
                        stg[e].y = ph2(f1.x, f1.y);
                    }
                }
            }

            float d0[8][4], d1[8][4];
#pragma unroll
            for (int i = 0; i < 8; i++)
#pragma unroll
                for (int j = 0; j < 4; j++) { d0[i][j] = 0.f; d1[i][j] = 0.f; }

            gemm_frag32((const uint2*)(U + 16384 + cur * 4096), 64,
                        (const uint2*)(U + sel * 8192), d0, d1,
                        mrow, colh, g, tig);

            const int brow = blk * 64;
#pragma unroll
            for (int rp = 0; rp < 2; rp++) {
                float (*dd)[4] = rp ? d1 : d0;
#pragma unroll
                for (int half = 0; half < 2; half++) {
                    const int row = brow + mrow + rp * 16 + g + half * 8;
                    if (row < NA) {
#pragma unroll
                        for (int nt = 0; nt < 8; nt++) {
                            const int col = colh * 64 + nt * 8 + 2 * tig;
                            *(unsigned*)&Cp[(size_t)row * HID + col] =
                                ph2(dd[nt][half * 2 + 0], dd[nt][half * 2 + 1]);
                        }
                    }
                }
            }

            if (nxt < KVB) {
                unsigned* A1 = U + 16384 + (cur ^ 1) * 4096;
#pragma unroll
                for (int e = 0; e < 8; e++) {
                    int row, smi, gof;
                    decode(e, row, smi, gof);
                    ((uint2*)A1)[smi] = stg[e];
                }
            }
            __syncthreads();
            blk = nxt;
            cur ^= 1;
        }
    } else {
        // ------------------------- Q persistent -------------------------
        pack_frags(Wq, U, 0, 128, 1 << 30, HID, 3, tid, 256);

        const int mrow = (warp >> 1) * 32;   // 4 rowgroups of 32
        const int colh = warp & 1;

        for (int blk = (int)blockIdx.x - KVC; blk < QBL; blk += QC) {
            const int brow = blk * 128;
            pack_frags(hQ, U + 8192, brow, 128, NQ, HID, 3, tid, 256);
            __syncthreads();

            float d0[8][4], d1[8][4];
#pragma unroll
            for (int i = 0; i < 8; i++)
#pragma unroll
                for (int j = 0; j < 4; j++) { d0[i][j] = 0.f; d1[i][j] = 0.f; }

            gemm_frag32((const uint2*)(U + 8192), 128,
                        (const uint2*)U, d0, d1, mrow, colh, g, tig);

#pragma unroll
            for (int rp = 0; rp < 2; rp++) {
                float (*dd)[4] = rp ? d1 : d0;
#pragma unroll
                for (int half = 0; half < 2; half++) {
                    const int row = brow + mrow + rp * 16 + g + half * 8;
                    if (row >= NQ) continue;
#pragma unroll
                    for (int nt = 0; nt < 8; nt++) {
                        const int col = colh * 64 + nt * 8 + 2 * tig;
                        *(float2*)&Cq[(size_t)row * HID + col] =
                            make_float2(dd[nt][half * 2 + 0],
                                        dd[nt][half * 2 + 1]);
                    }
                }
            }
            __syncthreads();
        }
    }
}

// ---------------------------------------------------------------------------
// mlp_fused: per block of 128 query rows:
//   H1 = relu(concat(h_query, agg) @ W1^T + b1)   (K=256, two A phases)
//   out = LN(h_query + H1 @ W2^T + b2) * gamma + beta
// Dyn smem 96KB: [W1 64K (later W2 32K)][A/H1 frags 32K]. LN scratch static.
// ---------------------------------------------------------------------------
__global__ __launch_bounds__(512, 2) void mlp_fused(
    const float* __restrict__ hQ, const float* __restrict__ agg,
    const float* __restrict__ W1, const float* __restrict__ b1,
    const float* __restrict__ W2, const float* __restrict__ b2,
    const float* __restrict__ gamma, const float* __restrict__ beta,
    float* __restrict__ out)
{
    extern __shared__ unsigned U[];
    __shared__ float2 scr[256];             // [128 rows][2 colhalves] (static)
    unsigned* AU = U + 16384;

    const int tid  = threadIdx.x;
    const int warp = tid >> 5;
    const int lane = tid & 31;
    const int g    = lane >> 2;
    const int tig  = lane & 3;
    const int mrow = (warp >> 1) * 16;
    const int colh = warp & 1;
    const int brow = blockIdx.x * 128;

    float d[8][4];
#pragma unroll
    for (int i = 0; i < 8; i++)
#pragma unroll
        for (int j = 0; j < 4; j++) d[i][j] = 0.f;

    // ---- MLP1: K=256 over [h_query | agg] ----
    pack_frags(W1, U, 0, 128, 1 << 30, 256, 4, tid, 512);   // 16 chunks
    pack_frags(hQ, AU, brow, 128, NQ, HID, 3, tid, 512);
    __syncthreads();
    gemm_frag((const uint2*)AU, 128, (const uint2*)U, 0, d, mrow, colh, g, tig);
    __syncthreads();
    pack_frags(agg, AU, brow, 128, NQ, HID, 3, tid, 512);
    __syncthreads();
    gemm_frag((const uint2*)AU, 128, (const uint2*)U, 8, d, mrow, colh, g, tig);
    __syncthreads();

    // ---- bias + ReLU; repack H1 tile as A-fragments; load W2 ----
#pragma unroll
    for (int half = 0; half < 2; half++) {
        const int rl = mrow + g + half * 8;
#pragma unroll
        for (int nt = 0; nt < 8; nt++) {
            const int col = colh * 64 + nt * 8 + 2 * tig;
            const float2 bi = *(const float2*)&b1[col];
            const float x0 = fmaxf(d[nt][half * 2 + 0] + bi.x, 0.f);
            const float x1 = fmaxf(d[nt][half * 2 + 1] + bi.y, 0.f);
            const int chunk = colh * 4 + (nt >> 1);
            AU[((chunk * 128 + rl) * 4 + tig) * 2 + (nt & 1)] = ph2(x0, x1);
        }
    }
    pack_frags(W2, U, 0, 128, 1 << 30, HID, 3, tid, 512);
    __syncthreads();

    // ---- MLP2 ----
#pragma unroll
    for (int i = 0; i < 8; i++)
#pragma unroll
        for (int j = 0; j < 4; j++) d[i][j] = 0.f;
    gemm_frag((const uint2*)AU, 128, (const uint2*)U, 0, d, mrow, colh, g, tig);

    // ---- b2 + residual + LayerNorm ----
    float psum[2], psq[2];
#pragma unroll
    for (int half = 0; half < 2; half++) {
        const int  row = brow + mrow + g + half * 8;
        const bool ok  = row < NQ;
        float s = 0.f, ss = 0.f;
#pragma unroll
        for (int nt = 0; nt < 8; nt++) {
            const int col = colh * 64 + nt * 8 + 2 * tig;
            const float2 bi = *(const float2*)&b2[col];
            float x0 = d[nt][half * 2 + 0] + bi.x;
            float x1 = d[nt][half * 2 + 1] + bi.y;
            if (ok) {
                const float2 rr = *(const float2*)&hQ[(size_t)row * HID + col];
                x0 += rr.x; x1 += rr.y;
            }
            d[nt][half * 2 + 0] = x0;
            d[nt][half * 2 + 1] = x1;
            s  += x0 + x1;
            ss += x0 * x0 + x1 * x1;
        }
        s  += __shfl_xor_sync(0xffffffffu, s, 1);
        s  += __shfl_xor_sync(0xffffffffu, s, 2);
        ss += __shfl_xor_sync(0xffffffffu, ss, 1);
        ss += __shfl_xor_sync(0xffffffffu, ss, 2);
        psum[half] = s; psq[half] = ss;
    }
#pragma unroll
    for (int half = 0; half < 2; half++) {
        const int rl = mrow + g + half * 8;
        if (tig == 0) scr[rl * 2 + colh] = make_float2(psum[half], psq[half]);
    }
    __syncthreads();
#pragma unroll
    for (int half = 0; half < 2; half++) {
        const int rl  = mrow + g + half * 8;
        const int row = brow + rl;
        const float2 f0 = scr[rl * 2 + 0];
        const float2 f1 = scr[rl * 2 + 1];
        const float mean = (f0.x + f1.x) * (1.f / 128.f);
        const float inv  = rsqrtf((f0.y + f1.y) * (1.f / 128.f)
                                  - mean * mean + 1e-5f);
        if (row >= NQ) continue;
#pragma unroll
        for (int nt = 0; nt < 8; nt++) {
            const int col = colh * 64 + nt * 8 + 2 * tig;
            const float2 gg = *(const float2*)&gamma[col];
            const float2 bb = *(const float2*)&beta[col];
            float2 o;
            o.x = (d[nt][half * 2 + 0] - mean) * inv * gg.x + bb.x;
            o.y = (d[nt][half * 2 + 1] - mean) * inv * gg.y + bb.y;
            *(float2*)&out[(size_t)row * HID + col] = o;
        }
    }
}

// ---------------------------------------------------------------------------
// Attention: one warp per query; lane l owns out dims [4l,4l+4) of head l/4.
// ---------------------------------------------------------------------------
__global__ __launch_bounds__(256) void attn_kernel(
    const float* __restrict__ Qq, const __half* __restrict__ Ka,
    const __half* __restrict__ Va, const float* __restrict__ edge_attr,
    const int*   __restrict__ src_idx, const float* __restrict__ W_rbf,
    float* __restrict__ agg)
{
    __shared__ float s_sc[8][8 * 36];
    __shared__ int   s_src[8][32];

    const int warp = threadIdx.x >> 5;
    const int lane = threadIdx.x & 31;
    const int q = blockIdx.x * 8 + warp;
    const int h   = lane >> 2;
    const int sm4 = lane & 3;

    const float4 q4 = *(const float4*)&Qq[(size_t)q * HID + lane * 4];
    const float4 wr = *(const float4*)&W_rbf[h * E_F + sm4 * 4];

    s_src[warp][lane] = src_idx[(size_t)q * KNN + lane];
    __syncwarp();

#pragma unroll
    for (int j = 0; j < KNN; j++) {
        const int sj = s_src[warp][j];
        const __half2* kr = (const __half2*)(Ka + (size_t)sj * HID);
        const float2 k01 = __half22float2(kr[lane * 2 + 0]);
        const float2 k23 = __half22float2(kr[lane * 2 + 1]);
        float dd = q4.x * k01.x + q4.y * k01.y + q4.z * k23.x + q4.w * k23.y;
        const float4 e4 = *(const float4*)
            &edge_attr[((size_t)q * KNN + j) * E_F + sm4 * 4];
        const float rr = e4.x * wr.x + e4.y * wr.y + e4.z * wr.z + e4.w * wr.w;
        float t = dd * 0.25f + rr;
        t += __shfl_xor_sync(0xffffffffu, t, 1);
        t += __shfl_xor_sync(0xffffffffu, t, 2);
        if (sm4 == 0) s_sc[warp][h * 36 + j] = t;
    }
    __syncwarp();

    float v[8];
    float m = -1e30f;
#pragma unroll
    for (int t = 0; t < 8; t++) {
        v[t] = s_sc[warp][h * 36 + sm4 + 4 * t];
        m = fmaxf(m, v[t]);
    }
    m = fmaxf(m, __shfl_xor_sync(0xffffffffu, m, 1));
    m = fmaxf(m, __shfl_xor_sync(0xffffffffu, m, 2));
    float sum = 0.f;
#pragma unroll
    for (int t = 0; t < 8; t++) { v[t] = __expf(v[t] - m); sum += v[t]; }
    sum += __shfl_xor_sync(0xffffffffu, sum, 1);
    sum += __shfl_xor_sync(0xffffffffu, sum, 2);
    const float inv = 1.f / (sum + 1e-16f);
#pragma unroll
    for (int t = 0; t < 8; t++) s_sc[warp][h * 36 + sm4 + 4 * t] = v[t] * inv;
    __syncwarp();

    float4 acc = make_float4(0.f, 0.f, 0.f, 0.f);
#pragma unroll
    for (int j = 0; j < KNN; j++) {
        const float a  = s_sc[warp][h * 36 + j];
        const int   sj = s_src[warp][j];
        const __half2* vr = (const __half2*)(Va + (size_t)sj * HID);
        const float2 v01 = __half22float2(vr[lane * 2 + 0]);
        const float2 v23 = __half22float2(vr[lane * 2 + 1]);
        acc.x = fmaf(a, v01.x, acc.x);
        acc.y = fmaf(a, v01.y, acc.y);
        acc.z = fmaf(a, v23.x, acc.z);
        acc.w = fmaf(a, v23.y, acc.w);
    }
    *(float4*)&agg[(size_t)q * HID + lane * 4] = acc;
}

// ---------------------------------------------------------------------------
extern "C" void kernel_launch(void* const* d_in, const int* in_sizes, int n_in,
                              void* d_out, int out_size)
{
    const float* h_atom    = (const float*)d_in[0];
    const float* h_query   = (const float*)d_in[1];
    const float* edge_attr = (const float*)d_in[2];
    const float* W_q       = (const float*)d_in[3];
    const float* W_k       = (const float*)d_in[4];
    const float* W_v       = (const float*)d_in[5];
    const float* W_rbf     = (const float*)d_in[6];
    const float* W1        = (const float*)d_in[7];
    const float* b1        = (const float*)d_in[8];
    const float* W2        = (const float*)d_in[9];
    const float* b2        = (const float*)d_in[10];
    const float* ln_gamma  = (const float*)d_in[11];
    const float* ln_beta   = (const float*)d_in[12];
    const int*   edge_index= (const int*)  d_in[13];   // [2,E]; row0 = src
    float* out = (float*)d_out;

    float *Qq, *agg;
    __half *Ka, *Va;
    cudaGetSymbolAddress((void**)&Qq,  g_Qq);
    cudaGetSymbolAddress((void**)&Ka,  g_Ka);
    cudaGetSymbolAddress((void**)&Va,  g_Va);
    cudaGetSymbolAddress((void**)&agg, g_agg);

    cudaFuncSetAttribute(proj_all,
                         cudaFuncAttributeMaxDynamicSharedMemorySize, 98304);
    cudaFuncSetAttribute(mlp_fused,
                         cudaFuncAttributeMaxDynamicSharedMemorySize, 98304);

    // persistent Q+K+V projections (weights packed once; 32x64 warp tiles)
    proj_all<<<KVC + QC, 256, 98304>>>(h_atom, h_query, W_k, W_v, W_q,
                                       Ka, Va, Qq);

    // segment-softmax attention + aggregation (dst[e] = e / KNN)
    attn_kernel<<<NQ / 8, 256>>>(Qq, Ka, Va, edge_attr, edge_index, W_rbf, agg);

    // fused MLP1 + ReLU + MLP2 + residual + LayerNorm
    mlp_fused<<<MLPB, 512, 98304>>>(h_query, agg, W1, b1, W2, b2,
                                    ln_gamma, ln_beta, out);
}

// round 12
// speedup vs baseline: 1.0220x; 1.0220x over previous
#include <cuda_runtime.h>
#include <cuda_fp16.h>

#define NQ    20000
#define NA    100000
#define KNN   32
#define HID   128
#define E_F   16

#define KVB   1563              // (NA+63)/64  KV row-blocks of 64
#define QBL   157               // (NQ+127)/128 Q row-blocks of 128
#define KVC   270               // persistent CTAs for KV
#define QC    26                // persistent CTAs for Q
#define MLPB  157

// ---------------- scratch (static device globals; no runtime alloc) ----------
__device__ __align__(16) float  g_Qq [NQ * HID];
__device__ __align__(16) __half g_Ka [NA * HID];
__device__ __align__(16) __half g_Va [NA * HID];
__device__ __align__(16) float  g_agg[NQ * HID];

// ------------------------- fp16 MMA helpers ----------------------------------
__device__ __forceinline__ unsigned ph2(float x, float y) {
    __half2 h = __floats2half2_rn(x, y);
    return *reinterpret_cast<unsigned*>(&h);
}
__device__ __forceinline__ void mma16(float* d, unsigned a0, unsigned a1,
                                      unsigned a2, unsigned a3,
                                      unsigned b0, unsigned b1) {
    asm volatile(
        "mma.sync.aligned.m16n8k16.row.col.f32.f16.f16.f32 "
        "{%0,%1,%2,%3}, {%4,%5,%6,%7}, {%8,%9}, {%0,%1,%2,%3};"
        : "+f"(d[0]), "+f"(d[1]), "+f"(d[2]), "+f"(d[3])
        : "r"(a0), "r"(a1), "r"(a2), "r"(a3), "r"(b0), "r"(b1));
}

// Fragment storage (uint2 per (chunk,row,tig)): idx = (chunk*ROWS + row)*4 + tig
//   .x = half2{ M[row][16c+2tig],   M[row][16c+2tig+1] }
//   .y = half2{ M[row][16c+2tig+8], M[row][16c+2tig+9] }

// Conflict-free packer: matrix S [rows x stride] fp32 -> fragments at U.
__device__ __forceinline__ void pack_frags(
    const float* __restrict__ S, unsigned* U, int rowbase, int rows,
    int maxrow, int stride, int lgNC, int tid, int nthr)
{
    const int NC = 1 << lgNC;
    const int total = rows * NC * 4;
    for (int idx = tid; idx < total; idx += nthr) {
        const int tig    = idx & 3;
        const int rlo    = (idx >> 2) & 7;
        const int rest   = idx >> 5;
        const int chunk  = rest & (NC - 1);
        const int rblock = rest >> lgNC;
        const int row    = rblock * 8 + rlo;
        const int gr     = rowbase + row;
        float2 f0 = make_float2(0.f, 0.f), f1 = f0;
        if (gr < maxrow) {
            const float* p = S + (size_t)gr * stride + chunk * 16 + tig * 2;
            f0 = *(const float2*)p;
            f1 = *(const float2*)(p + 8);
        }
        uint2 v;
        v.x = ph2(f0.x, f0.y);
        v.y = ph2(f1.x, f1.y);
        ((uint2*)U)[(chunk * rows + row) * 4 + tig] = v;
    }
}

// 16x64 warp-tile GEMM over 8 k16 chunks.
__device__ __forceinline__ void gemm_frag(const uint2* __restrict__ AF, int AR,
                                          const uint2* __restrict__ WF, int wcoff,
                                          float d[8][4], int mrow, int colh,
                                          int g, int tig) {
#pragma unroll
    for (int c = 0; c < 8; c++) {
        const uint2 aA = AF[(c * AR + mrow + g) * 4 + tig];
        const uint2 aB = AF[(c * AR + mrow + 8 + g) * 4 + tig];
#pragma unroll
        for (int nt = 0; nt < 8; nt++) {
            const int n = colh * 64 + nt * 8 + g;
            const uint2 b = WF[((wcoff + c) * 128 + n) * 4 + tig];
            mma16(d[nt], aA.x, aB.x, aA.y, aB.y, b.x, b.y);
        }
    }
}

// ---------------------------------------------------------------------------
// proj_all: 296 persistent CTAs, 512 threads, 2 CTAs/SM.
// CTAs [0,KVC): KV blocks (BM=64). The CTA splits into 4 INDEPENDENT groups
// of 4 warps; group gid owns rows [gid*16, gid*16+16) of every block and its
// 4 warps are {K,V} x {colh0,colh1}. Each group has its own double-buffered
// A slice and syncs only via bar.sync(1+gid, 128) -> groups slide freely,
// overlapping one group's LDG stall with another's MMAs.
// CTAs [KVC,KVC+QC): Q blocks (BM=128), CTA-wide as before.
// Dyn smem 96KB: [Wk 32K][Wv 32K][A 4x2x4K] / Q: [Wq 32K][A 32K].
// ---------------------------------------------------------------------------
__global__ __launch_bounds__(512, 2) void proj_all(
    const float* __restrict__ hA, const float* __restrict__ hQ,
    const float* __restrict__ Wk, const float* __restrict__ Wv,
    const float* __restrict__ Wq,
    __half* __restrict__ Ck, __half* __restrict__ Cv, float* __restrict__ Cq)
{
    extern __shared__ unsigned U[];
    const int tid  = threadIdx.x;
    const int warp = tid >> 5;
    const int lane = tid & 31;
    const int g    = lane >> 2;
    const int tig  = lane & 3;

    if (blockIdx.x < KVC) {
        // ------------------------- KV persistent -------------------------
        pack_frags(Wk, U,        0, 128, 1 << 30, HID, 3, tid, 512);
        pack_frags(Wv, U + 8192, 0, 128, 1 << 30, HID, 3, tid, 512);
        __syncthreads();          // weights visible to all groups

        const int gid  = warp >> 2;          // group 0..3 -> rows gid*16
        const int sel  = (warp >> 1) & 1;    // 0=K, 1=V
        const int colh = warp & 1;
        const int gt   = tid & 127;          // thread id within group
        __half* Cp = sel ? Cv : Ck;

        // group A buffers: U + 16384 + (gid*2 + buf)*1024 (uint units, 4KB)
        unsigned* Abase = U + 16384 + gid * 2048;

        // per-thread staging decode: 4 elements, idx = gt + e*128
        // tig=idx&3, rlo=(idx>>2)&7, chunk=(idx>>5)&7, rblk=idx>>8 (0..1)
        auto decode = [&](int e, int& row, int& smi, int& gof) {
            const int idx  = gt + e * 128;          // < 512
            const int tg   = idx & 3;
            const int rlo  = (idx >> 2) & 7;
            const int rest = idx >> 5;
            const int chk  = rest & 7;
            row = (rest >> 3) * 8 + rlo;            // 0..15
            smi = (chk * 16 + row) * 4 + tg;        // uint2 index
            gof = row * HID + chk * 16 + tg * 2;    // float offset in slice
        };

        // prologue: stage block0 slice into buf0
        int blk = blockIdx.x;
        {
            const int srow = blk * 64 + gid * 16;
#pragma unroll
            for (int e = 0; e < 4; e++) {
                int row, smi, gof;
                decode(e, row, smi, gof);
                uint2 v = make_uint2(0u, 0u);
                if (srow + row < NA) {
                    const float* p = hA + (size_t)srow * HID + gof;
                    const float2 f0 = *(const float2*)p;
                    const float2 f1 = *(const float2*)(p + 8);
                    v.x = ph2(f0.x, f0.y);
                    v.y = ph2(f1.x, f1.y);
                }
                ((uint2*)Abase)[smi] = v;
            }
        }
        asm volatile("bar.sync %0, 128;" :: "r"(1 + gid) : "memory");

        int cur = 0;
        while (blk < KVB) {
            const int nxt = blk + KVC;
            // stage next block's slice in registers (overlaps MMAs below)
            uint2 stg[4];
            if (nxt < KVB) {
                const int srow = nxt * 64 + gid * 16;
#pragma unroll
                for (int e = 0; e < 4; e++) {
                    int row, smi, gof;
                    decode(e, row, smi, gof);
                    stg[e] = make_uint2(0u, 0u);
                    if (srow + row < NA) {
                        const float* p = hA + (size_t)srow * HID + gof;
                        const float2 f0 = *(const float2*)p;
                        const float2 f1 = *(const float2*)(p + 8);
                        stg[e].x = ph2(f0.x, f0.y);
                        stg[e].y = ph2(f1.x, f1.y);
                    }
                }
            }

            float d[8][4];
#pragma unroll
            for (int i = 0; i < 8; i++)
#pragma unroll
                for (int j = 0; j < 4; j++) d[i][j] = 0.f;

            gemm_frag((const uint2*)(Abase + cur * 1024), 16,
                      (const uint2*)(U + sel * 8192), 0, d, 0, colh, g, tig);

            const int brow = blk * 64 + gid * 16;
#pragma unroll
            for (int half = 0; half < 2; half++) {
                const int row = brow + g + half * 8;
                if (row < NA) {
#pragma unroll
                    for (int nt = 0; nt < 8; nt++) {
                        const int col = colh * 64 + nt * 8 + 2 * tig;
                        *(unsigned*)&Cp[(size_t)row * HID + col] =
                            ph2(d[nt][half * 2 + 0], d[nt][half * 2 + 1]);
                    }
                }
            }

            if (nxt < KVB) {
                unsigned* A1 = Abase + (cur ^ 1) * 1024;
#pragma unroll
                for (int e = 0; e < 4; e++) {
                    int row, smi, gof;
                    decode(e, row, smi, gof);
                    ((uint2*)A1)[smi] = stg[e];
                }
            }
            asm volatile("bar.sync %0, 128;" :: "r"(1 + gid) : "memory");
            blk = nxt;
            cur ^= 1;
        }
    } else {
        // ------------------------- Q persistent -------------------------
        pack_frags(Wq, U, 0, 128, 1 << 30, HID, 3, tid, 512);

        const int mrow = (warp >> 1) * 16;
        const int colh = warp & 1;

        for (int blk = (int)blockIdx.x - KVC; blk < QBL; blk += QC) {
            const int brow = blk * 128;
            pack_frags(hQ, U + 8192, brow, 128, NQ, HID, 3, tid, 512);
            __syncthreads();

            float d[8][4];
#pragma unroll
            for (int i = 0; i < 8; i++)
#pragma unroll
                for (int j = 0; j < 4; j++) d[i][j] = 0.f;

            gemm_frag((const uint2*)(U + 8192), 128,
                      (const uint2*)U, 0, d, mrow, colh, g, tig);

#pragma unroll
            for (int half = 0; half < 2; half++) {
                const int row = brow + mrow + g + half * 8;
                if (row >= NQ) continue;
#pragma unroll
                for (int nt = 0; nt < 8; nt++) {
                    const int col = colh * 64 + nt * 8 + 2 * tig;
                    *(float2*)&Cq[(size_t)row * HID + col] =
                        make_float2(d[nt][half * 2 + 0], d[nt][half * 2 + 1]);
                }
            }
            __syncthreads();
        }
    }
}

// ---------------------------------------------------------------------------
// mlp_fused: per block of 128 query rows:
//   H1 = relu(concat(h_query, agg) @ W1^T + b1)   (K=256, two A phases)
//   out = LN(h_query + H1 @ W2^T + b2) * gamma + beta
// Dyn smem 96KB: [W1 64K (later W2 32K)][A/H1 frags 32K]. LN scratch static.
// ---------------------------------------------------------------------------
__global__ __launch_bounds__(512, 2) void mlp_fused(
    const float* __restrict__ hQ, const float* __restrict__ agg,
    const float* __restrict__ W1, const float* __restrict__ b1,
    const float* __restrict__ W2, const float* __restrict__ b2,
    const float* __restrict__ gamma, const float* __restrict__ beta,
    float* __restrict__ out)
{
    extern __shared__ unsigned U[];
    __shared__ float2 scr[256];
    unsigned* AU = U + 16384;

    const int tid  = threadIdx.x;
    const int warp = tid >> 5;
    const int lane = tid & 31;
    const int g    = lane >> 2;
    const int tig  = lane & 3;
    const int mrow = (warp >> 1) * 16;
    const int colh = warp & 1;
    const int brow = blockIdx.x * 128;

    float d[8][4];
#pragma unroll
    for (int i = 0; i < 8; i++)
#pragma unroll
        for (int j = 0; j < 4; j++) d[i][j] = 0.f;

    pack_frags(W1, U, 0, 128, 1 << 30, 256, 4, tid, 512);
    pack_frags(hQ, AU, brow, 128, NQ, HID, 3, tid, 512);
    __syncthreads();
    gemm_frag((const uint2*)AU, 128, (const uint2*)U, 0, d, mrow, colh, g, tig);
    __syncthreads();
    pack_frags(agg, AU, brow, 128, NQ, HID, 3, tid, 512);
    __syncthreads();
    gemm_frag((const uint2*)AU, 128, (const uint2*)U, 8, d, mrow, colh, g, tig);
    __syncthreads();

#pragma unroll
    for (int half = 0; half < 2; half++) {
        const int rl = mrow + g + half * 8;
#pragma unroll
        for (int nt = 0; nt < 8; nt++) {
            const int col = colh * 64 + nt * 8 + 2 * tig;
            const float2 bi = *(const float2*)&b1[col];
            const float x0 = fmaxf(d[nt][half * 2 + 0] + bi.x, 0.f);
            const float x1 = fmaxf(d[nt][half * 2 + 1] + bi.y, 0.f);
            const int chunk = colh * 4 + (nt >> 1);
            AU[((chunk * 128 + rl) * 4 + tig) * 2 + (nt & 1)] = ph2(x0, x1);
        }
    }
    pack_frags(W2, U, 0, 128, 1 << 30, HID, 3, tid, 512);
    __syncthreads();

#pragma unroll
    for (int i = 0; i < 8; i++)
#pragma unroll
        for (int j = 0; j < 4; j++) d[i][j] = 0.f;
    gemm_frag((const uint2*)AU, 128, (const uint2*)U, 0, d, mrow, colh, g, tig);

    float psum[2], psq[2];
#pragma unroll
    for (int half = 0; half < 2; half++) {
        const int  row = brow + mrow + g + half * 8;
        const bool ok  = row < NQ;
        float s = 0.f, ss = 0.f;
#pragma unroll
        for (int nt = 0; nt < 8; nt++) {
            const int col = colh * 64 + nt * 8 + 2 * tig;
            const float2 bi = *(const float2*)&b2[col];
            float x0 = d[nt][half * 2 + 0] + bi.x;
            float x1 = d[nt][half * 2 + 1] + bi.y;
            if (ok) {
                const float2 rr = *(const float2*)&hQ[(size_t)row * HID + col];
                x0 += rr.x; x1 += rr.y;
            }
            d[nt][half * 2 + 0] = x0;
            d[nt][half * 2 + 1] = x1;
            s  += x0 + x1;
            ss += x0 * x0 + x1 * x1;
        }
        s  += __shfl_xor_sync(0xffffffffu, s, 1);
        s  += __shfl_xor_sync(0xffffffffu, s, 2);
        ss += __shfl_xor_sync(0xffffffffu, ss, 1);
        ss += __shfl_xor_sync(0xffffffffu, ss, 2);
        psum[half] = s; psq[half] = ss;
    }
#pragma unroll
    for (int half = 0; half < 2; half++) {
        const int rl = mrow + g + half * 8;
        if (tig == 0) scr[rl * 2 + colh] = make_float2(psum[half], psq[half]);
    }
    __syncthreads();
#pragma unroll
    for (int half = 0; half < 2; half++) {
        const int rl  = mrow + g + half * 8;
        const int row = brow + rl;
        const float2 f0 = scr[rl * 2 + 0];
        const float2 f1 = scr[rl * 2 + 1];
        const float mean = (f0.x + f1.x) * (1.f / 128.f);
        const float inv  = rsqrtf((f0.y + f1.y) * (1.f / 128.f)
                                  - mean * mean + 1e-5f);
        if (row >= NQ) continue;
#pragma unroll
        for (int nt = 0; nt < 8; nt++) {
            const int col = colh * 64 + nt * 8 + 2 * tig;
            const float2 gg = *(const float2*)&gamma[col];
            const float2 bb = *(const float2*)&beta[col];
            float2 o;
            o.x = (d[nt][half * 2 + 0] - mean) * inv * gg.x + bb.x;
            o.y = (d[nt][half * 2 + 1] - mean) * inv * gg.y + bb.y;
            *(float2*)&out[(size_t)row * HID + col] = o;
        }
    }
}

// ---------------------------------------------------------------------------
// Attention: one warp per query; lane l owns out dims [4l,4l+4) of head l/4.
// ---------------------------------------------------------------------------
__global__ __launch_bounds__(256) void attn_kernel(
    const float* __restrict__ Qq, const __half* __restrict__ Ka,
    const __half* __restrict__ Va, const float* __restrict__ edge_attr,
    const int*   __restrict__ src_idx, const float* __restrict__ W_rbf,
    float* __restrict__ agg)
{
    __shared__ float s_sc[8][8 * 36];
    __shared__ int   s_src[8][32];

    const int warp = threadIdx.x >> 5;
    const int lane = threadIdx.x & 31;
    const int q = blockIdx.x * 8 + warp;
    const int h   = lane >> 2;
    const int sm4 = lane & 3;

    const float4 q4 = *(const float4*)&Qq[(size_t)q * HID + lane * 4];
    const float4 wr = *(const float4*)&W_rbf[h * E_F + sm4 * 4];

    s_src[warp][lane] = src_idx[(size_t)q * KNN + lane];
    __syncwarp();

#pragma unroll
    for (int j = 0; j < KNN; j++) {
        const int sj = s_src[warp][j];
        const __half2* kr = (const __half2*)(Ka + (size_t)sj * HID);
        const float2 k01 = __half22float2(kr[lane * 2 + 0]);
        const float2 k23 = __half22float2(kr[lane * 2 + 1]);
        float dd = q4.x * k01.x + q4.y * k01.y + q4.z * k23.x + q4.w * k23.y;
        const float4 e4 = *(const float4*)
            &edge_attr[((size_t)q * KNN + j) * E_F + sm4 * 4];
        const float rr = e4.x * wr.x + e4.y * wr.y + e4.z * wr.z + e4.w * wr.w;
        float t = dd * 0.25f + rr;
        t += __shfl_xor_sync(0xffffffffu, t, 1);
        t += __shfl_xor_sync(0xffffffffu, t, 2);
        if (sm4 == 0) s_sc[warp][h * 36 + j] = t;
    }
    __syncwarp();

    float v[8];
    float m = -1e30f;
#pragma unroll
    for (int t = 0; t < 8; t++) {
        v[t] = s_sc[warp][h * 36 + sm4 + 4 * t];
        m = fmaxf(m, v[t]);
    }
    m = fmaxf(m, __shfl_xor_sync(0xffffffffu, m, 1));
    m = fmaxf(m, __shfl_xor_sync(0xffffffffu, m, 2));
    float sum = 0.f;
#pragma unroll
    for (int t = 0; t < 8; t++) { v[t] = __expf(v[t] - m); sum += v[t]; }
    sum += __shfl_xor_sync(0xffffffffu, sum, 1);
    sum += __shfl_xor_sync(0xffffffffu, sum, 2);
    const float inv = 1.f / (sum + 1e-16f);
#pragma unroll
    for (int t = 0; t < 8; t++) s_sc[warp][h * 36 + sm4 + 4 * t] = v[t] * inv;
    __syncwarp();

    float4 acc = make_float4(0.f, 0.f, 0.f, 0.f);
#pragma unroll
    for (int j = 0; j < KNN; j++) {
        const float a  = s_sc[warp][h * 36 + j];
        const int   sj = s_src[warp][j];
        const __half2* vr = (const __half2*)(Va + (size_t)sj * HID);
        const float2 v01 = __half22float2(vr[lane * 2 + 0]);
        const float2 v23 = __half22float2(vr[lane * 2 + 1]);
        acc.x = fmaf(a, v01.x, acc.x);
        acc.y = fmaf(a, v01.y, acc.y);
        acc.z = fmaf(a, v23.x, acc.z);
        acc.w = fmaf(a, v23.y, acc.w);
    }
    *(float4*)&agg[(size_t)q * HID + lane * 4] = acc;
}

// ---------------------------------------------------------------------------
extern "C" void kernel_launch(void* const* d_in, const int* in_sizes, int n_in,
                              void* d_out, int out_size)
{
    const float* h_atom    = (const float*)d_in[0];
    const float* h_query   = (const float*)d_in[1];
    const float* edge_attr = (const float*)d_in[2];
    const float* W_q       = (const float*)d_in[3];
    const float* W_k       = (const float*)d_in[4];
    const float* W_v       = (const float*)d_in[5];
    const float* W_rbf     = (const float*)d_in[6];
    const float* W1        = (const float*)d_in[7];
    const float* b1        = (const float*)d_in[8];
    const float* W2        = (const float*)d_in[9];
    const float* b2        = (const float*)d_in[10];
    const float* ln_gamma  = (const float*)d_in[11];
    const float* ln_beta   = (const float*)d_in[12];
    const int*   edge_index= (const int*)  d_in[13];   // [2,E]; row0 = src
    float* out = (float*)d_out;

    float *Qq, *agg;
    __half *Ka, *Va;
    cudaGetSymbolAddress((void**)&Qq,  g_Qq);
    cudaGetSymbolAddress((void**)&Ka,  g_Ka);
    cudaGetSymbolAddress((void**)&Va,  g_Va);
    cudaGetSymbolAddress((void**)&agg, g_agg);

    cudaFuncSetAttribute(proj_all,
                         cudaFuncAttributeMaxDynamicSharedMemorySize, 98304);
    cudaFuncSetAttribute(mlp_fused,
                         cudaFuncAttributeMaxDynamicSharedMemorySize, 98304);

    // persistent Q+K+V projections (weights packed once; decoupled quad-groups)
    proj_all<<<KVC + QC, 512, 98304>>>(h_atom, h_query, W_k, W_v, W_q,
                                       Ka, Va, Qq);

    // segment-softmax attention + aggregation (dst[e] = e / KNN)
    attn_kernel<<<NQ / 8, 256>>>(Qq, Ka, Va, edge_attr, edge_index, W_rbf, agg);

    // fused MLP1 + ReLU + MLP2 + residual + LayerNorm
    mlp_fused<<<MLPB, 512, 98304>>>(h_query, agg, W1, b1, W2, b2,
                                    ln_gamma, ln_beta, out);
}

// round 13
// speedup vs baseline: 1.0331x; 1.0109x over previous
#include <cuda_runtime.h>
#include <cuda_fp16.h>

#define NQ    20000
#define NA    100000
#define KNN   32
#define HID   128
#define E_F   16

#define KVB   1563              // (NA+63)/64  KV row-blocks of 64
#define QBL   157               // (NQ+127)/128 Q row-blocks of 128
#define KVC   270               // persistent CTAs for KV
#define QC    26                // persistent CTAs for Q
#define MLPB  157

// ---------------- scratch (static device globals; no runtime alloc) ----------
__device__ __align__(16) float  g_Qq [NQ * HID];
__device__ __align__(16) __half g_Ka [NA * HID];
__device__ __align__(16) __half g_Va [NA * HID];
__device__ __align__(16) float  g_agg[NQ * HID];

// ------------------------- fp16 MMA helpers ----------------------------------
__device__ __forceinline__ unsigned ph2(float x, float y) {
    __half2 h = __floats2half2_rn(x, y);
    return *reinterpret_cast<unsigned*>(&h);
}
__device__ __forceinline__ void mma16(float* d, unsigned a0, unsigned a1,
                                      unsigned a2, unsigned a3,
                                      unsigned b0, unsigned b1) {
    asm volatile(
        "mma.sync.aligned.m16n8k16.row.col.f32.f16.f16.f32 "
        "{%0,%1,%2,%3}, {%4,%5,%6,%7}, {%8,%9}, {%0,%1,%2,%3};"
        : "+f"(d[0]), "+f"(d[1]), "+f"(d[2]), "+f"(d[3])
        : "r"(a0), "r"(a1), "r"(a2), "r"(a3), "r"(b0), "r"(b1));
}

// Fragment storage (uint2 per (chunk,row,tig)): idx = (chunk*ROWS + row)*4 + tig
__device__ __forceinline__ void pack_frags(
    const float* __restrict__ S, unsigned* U, int rowbase, int rows,
    int maxrow, int stride, int lgNC, int tid, int nthr)
{
    const int NC = 1 << lgNC;
    const int total = rows * NC * 4;
    for (int idx = tid; idx < total; idx += nthr) {
        const int tig    = idx & 3;
        const int rlo    = (idx >> 2) & 7;
        const int rest   = idx >> 5;
        const int chunk  = rest & (NC - 1);
        const int rblock = rest >> lgNC;
        const int row    = rblock * 8 + rlo;
        const int gr     = rowbase + row;
        float2 f0 = make_float2(0.f, 0.f), f1 = f0;
        if (gr < maxrow) {
            const float* p = S + (size_t)gr * stride + chunk * 16 + tig * 2;
            f0 = *(const float2*)p;
            f1 = *(const float2*)(p + 8);
        }
        uint2 v;
        v.x = ph2(f0.x, f0.y);
        v.y = ph2(f1.x, f1.y);
        ((uint2*)U)[(chunk * rows + row) * 4 + tig] = v;
    }
}

// 16x64 warp-tile GEMM over 8 k16 chunks.
__device__ __forceinline__ void gemm_frag(const uint2* __restrict__ AF, int AR,
                                          const uint2* __restrict__ WF, int wcoff,
                                          float d[8][4], int mrow, int colh,
                                          int g, int tig) {
#pragma unroll
    for (int c = 0; c < 8; c++) {
        const uint2 aA = AF[(c * AR + mrow + g) * 4 + tig];
        const uint2 aB = AF[(c * AR + mrow + 8 + g) * 4 + tig];
#pragma unroll
        for (int nt = 0; nt < 8; nt++) {
            const int n = colh * 64 + nt * 8 + g;
            const uint2 b = WF[((wcoff + c) * 128 + n) * 4 + tig];
            mma16(d[nt], aA.x, aB.x, aA.y, aB.y, b.x, b.y);
        }
    }
}

// ---------------------------------------------------------------------------
// proj_all (unchanged from R12): 296 persistent CTAs, 512 threads, 2 CTAs/SM.
// ---------------------------------------------------------------------------
__global__ __launch_bounds__(512, 2) void proj_all(
    const float* __restrict__ hA, const float* __restrict__ hQ,
    const float* __restrict__ Wk, const float* __restrict__ Wv,
    const float* __restrict__ Wq,
    __half* __restrict__ Ck, __half* __restrict__ Cv, float* __restrict__ Cq)
{
    extern __shared__ unsigned U[];
    const int tid  = threadIdx.x;
    const int warp = tid >> 5;
    const int lane = tid & 31;
    const int g    = lane >> 2;
    const int tig  = lane & 3;

    if (blockIdx.x < KVC) {
        pack_frags(Wk, U,        0, 128, 1 << 30, HID, 3, tid, 512);
        pack_frags(Wv, U + 8192, 0, 128, 1 << 30, HID, 3, tid, 512);
        __syncthreads();

        const int gid  = warp >> 2;
        const int sel  = (warp >> 1) & 1;
        const int colh = warp & 1;
        const int gt   = tid & 127;
        __half* Cp = sel ? Cv : Ck;

        unsigned* Abase = U + 16384 + gid * 2048;

        auto decode = [&](int e, int& row, int& smi, int& gof) {
            const int idx  = gt + e * 128;
            const int tg   = idx & 3;
            const int rlo  = (idx >> 2) & 7;
            const int rest = idx >> 5;
            const int chk  = rest & 7;
            row = (rest >> 3) * 8 + rlo;
            smi = (chk * 16 + row) * 4 + tg;
            gof = row * HID + chk * 16 + tg * 2;
        };

        int blk = blockIdx.x;
        {
            const int srow = blk * 64 + gid * 16;
#pragma unroll
            for (int e = 0; e < 4; e++) {
                int row, smi, gof;
                decode(e, row, smi, gof);
                uint2 v = make_uint2(0u, 0u);
                if (srow + row < NA) {
                    const float* p = hA + (size_t)srow * HID + gof;
                    const float2 f0 = *(const float2*)p;
                    const float2 f1 = *(const float2*)(p + 8);
                    v.x = ph2(f0.x, f0.y);
                    v.y = ph2(f1.x, f1.y);
                }
                ((uint2*)Abase)[smi] = v;
            }
        }
        asm volatile("bar.sync %0, 128;" :: "r"(1 + gid) : "memory");

        int cur = 0;
        while (blk < KVB) {
            const int nxt = blk + KVC;
            uint2 stg[4];
            if (nxt < KVB) {
                const int srow = nxt * 64 + gid * 16;
#pragma unroll
                for (int e = 0; e < 4; e++) {
                    int row, smi, gof;
                    decode(e, row, smi, gof);
                    stg[e] = make_uint2(0u, 0u);
                    if (srow + row < NA) {
                        const float* p = hA + (size_t)srow * HID + gof;
                        const float2 f0 = *(const float2*)p;
                        const float2 f1 = *(const float2*)(p + 8);
                        stg[e].x = ph2(f0.x, f0.y);
                        stg[e].y = ph2(f1.x, f1.y);
                    }
                }
            }

            float d[8][4];
#pragma unroll
            for (int i = 0; i < 8; i++)
#pragma unroll
                for (int j = 0; j < 4; j++) d[i][j] = 0.f;

            gemm_frag((const uint2*)(Abase + cur * 1024), 16,
                      (const uint2*)(U + sel * 8192), 0, d, 0, colh, g, tig);

            const int brow = blk * 64 + gid * 16;
#pragma unroll
            for (int half = 0; half < 2; half++) {
                const int row = brow + g + half * 8;
                if (row < NA) {
#pragma unroll
                    for (int nt = 0; nt < 8; nt++) {
                        const int col = colh * 64 + nt * 8 + 2 * tig;
                        *(unsigned*)&Cp[(size_t)row * HID + col] =
                            ph2(d[nt][half * 2 + 0], d[nt][half * 2 + 1]);
                    }
                }
            }

            if (nxt < KVB) {
                unsigned* A1 = Abase + (cur ^ 1) * 1024;
#pragma unroll
                for (int e = 0; e < 4; e++) {
                    int row, smi, gof;
                    decode(e, row, smi, gof);
                    ((uint2*)A1)[smi] = stg[e];
                }
            }
            asm volatile("bar.sync %0, 128;" :: "r"(1 + gid) : "memory");
            blk = nxt;
            cur ^= 1;
        }
    } else {
        pack_frags(Wq, U, 0, 128, 1 << 30, HID, 3, tid, 512);

        const int mrow = (warp >> 1) * 16;
        const int colh = warp & 1;

        for (int blk = (int)blockIdx.x - KVC; blk < QBL; blk += QC) {
            const int brow = blk * 128;
            pack_frags(hQ, U + 8192, brow, 128, NQ, HID, 3, tid, 512);
            __syncthreads();

            float d[8][4];
#pragma unroll
            for (int i = 0; i < 8; i++)
#pragma unroll
                for (int j = 0; j < 4; j++) d[i][j] = 0.f;

            gemm_frag((const uint2*)(U + 8192), 128,
                      (const uint2*)U, 0, d, mrow, colh, g, tig);

#pragma unroll
            for (int half = 0; half < 2; half++) {
                const int row = brow + mrow + g + half * 8;
                if (row >= NQ) continue;
#pragma unroll
                for (int nt = 0; nt < 8; nt++) {
                    const int col = colh * 64 + nt * 8 + 2 * tig;
                    *(float2*)&Cq[(size_t)row * HID + col] =
                        make_float2(d[nt][half * 2 + 0], d[nt][half * 2 + 1]);
                }
            }
            __syncthreads();
        }
    }
}

// ---------------------------------------------------------------------------
// mlp_fused (unchanged from R12)
// ---------------------------------------------------------------------------
__global__ __launch_bounds__(512, 2) void mlp_fused(
    const float* __restrict__ hQ, const float* __restrict__ agg,
    const float* __restrict__ W1, const float* __restrict__ b1,
    const float* __restrict__ W2, const float* __restrict__ b2,
    const float* __restrict__ gamma, const float* __restrict__ beta,
    float* __restrict__ out)
{
    extern __shared__ unsigned U[];
    __shared__ float2 scr[256];
    unsigned* AU = U + 16384;

    const int tid  = threadIdx.x;
    const int warp = tid >> 5;
    const int lane = tid & 31;
    const int g    = lane >> 2;
    const int tig  = lane & 3;
    const int mrow = (warp >> 1) * 16;
    const int colh = warp & 1;
    const int brow = blockIdx.x * 128;

    float d[8][4];
#pragma unroll
    for (int i = 0; i < 8; i++)
#pragma unroll
        for (int j = 0; j < 4; j++) d[i][j] = 0.f;

    pack_frags(W1, U, 0, 128, 1 << 30, 256, 4, tid, 512);
    pack_frags(hQ, AU, brow, 128, NQ, HID, 3, tid, 512);
    __syncthreads();
    gemm_frag((const uint2*)AU, 128, (const uint2*)U, 0, d, mrow, colh, g, tig);
    __syncthreads();
    pack_frags(agg, AU, brow, 128, NQ, HID, 3, tid, 512);
    __syncthreads();
    gemm_frag((const uint2*)AU, 128, (const uint2*)U, 8, d, mrow, colh, g, tig);
    __syncthreads();

#pragma unroll
    for (int half = 0; half < 2; half++) {
        const int rl = mrow + g + half * 8;
#pragma unroll
        for (int nt = 0; nt < 8; nt++) {
            const int col = colh * 64 + nt * 8 + 2 * tig;
            const float2 bi = *(const float2*)&b1[col];
            const float x0 = fmaxf(d[nt][half * 2 + 0] + bi.x, 0.f);
            const float x1 = fmaxf(d[nt][half * 2 + 1] + bi.y, 0.f);
            const int chunk = colh * 4 + (nt >> 1);
            AU[((chunk * 128 + rl) * 4 + tig) * 2 + (nt & 1)] = ph2(x0, x1);
        }
    }
    pack_frags(W2, U, 0, 128, 1 << 30, HID, 3, tid, 512);
    __syncthreads();

#pragma unroll
    for (int i = 0; i < 8; i++)
#pragma unroll
        for (int j = 0; j < 4; j++) d[i][j] = 0.f;
    gemm_frag((const uint2*)AU, 128, (const uint2*)U, 0, d, mrow, colh, g, tig);

    float psum[2], psq[2];
#pragma unroll
    for (int half = 0; half < 2; half++) {
        const int  row = brow + mrow + g + half * 8;
        const bool ok  = row < NQ;
        float s = 0.f, ss = 0.f;
#pragma unroll
        for (int nt = 0; nt < 8; nt++) {
            const int col = colh * 64 + nt * 8 + 2 * tig;
            const float2 bi = *(const float2*)&b2[col];
            float x0 = d[nt][half * 2 + 0] + bi.x;
            float x1 = d[nt][half * 2 + 1] + bi.y;
            if (ok) {
                const float2 rr = *(const float2*)&hQ[(size_t)row * HID + col];
                x0 += rr.x; x1 += rr.y;
            }
            d[nt][half * 2 + 0] = x0;
            d[nt][half * 2 + 1] = x1;
            s  += x0 + x1;
            ss += x0 * x0 + x1 * x1;
        }
        s  += __shfl_xor_sync(0xffffffffu, s, 1);
        s  += __shfl_xor_sync(0xffffffffu, s, 2);
        ss += __shfl_xor_sync(0xffffffffu, ss, 1);
        ss += __shfl_xor_sync(0xffffffffu, ss, 2);
        psum[half] = s; psq[half] = ss;
    }
#pragma unroll
    for (int half = 0; half < 2; half++) {
        const int rl = mrow + g + half * 8;
        if (tig == 0) scr[rl * 2 + colh] = make_float2(psum[half], psq[half]);
    }
    __syncthreads();
#pragma unroll
    for (int half = 0; half < 2; half++) {
        const int rl  = mrow + g + half * 8;
        const int row = brow + rl;
        const float2 f0 = scr[rl * 2 + 0];
        const float2 f1 = scr[rl * 2 + 1];
        const float mean = (f0.x + f1.x) * (1.f / 128.f);
        const float inv  = rsqrtf((f0.y + f1.y) * (1.f / 128.f)
                                  - mean * mean + 1e-5f);
        if (row >= NQ) continue;
#pragma unroll
        for (int nt = 0; nt < 8; nt++) {
            const int col = colh * 64 + nt * 8 + 2 * tig;
            const float2 gg = *(const float2*)&gamma[col];
            const float2 bb = *(const float2*)&beta[col];
            float2 o;
            o.x = (d[nt][half * 2 + 0] - mean) * inv * gg.x + bb.x;
            o.y = (d[nt][half * 2 + 1] - mean) * inv * gg.y + bb.y;
            *(float2*)&out[(size_t)row * HID + col] = o;
        }
    }
}

// ---------------------------------------------------------------------------
// Attention v2: one warp per query. Lane (h = lane>>2, sm4 = lane&3) computes
// the FULL score (16-dim K-dot + 16-feature rbf) of its 8 owned edges
// (j = sm4 + 4t) with ZERO shuffles in the score phase -> 8 independent 32B
// K-gathers in flight per lane. edge_attr staged cooperatively in smem.
// Softmax: in-lane over 8 + 4 shfls across the sm4 group. V-agg unchanged.
// ---------------------------------------------------------------------------
__global__ __launch_bounds__(256) void attn_kernel(
    const float* __restrict__ Qq, const __half* __restrict__ Ka,
    const __half* __restrict__ Va, const float* __restrict__ edge_attr,
    const int*   __restrict__ src_idx, const float* __restrict__ W_rbf,
    float* __restrict__ agg)
{
    __shared__ float  s_al[8][8 * 36];     // alphas, head-sliced, pad 36
    __shared__ int    s_src[8][32];
    __shared__ float4 s_ea[8][128];        // edge_attr: 32 edges x 16 f32

    const int warp = threadIdx.x >> 5;
    const int lane = threadIdx.x & 31;
    const int q   = blockIdx.x * 8 + warp;
    const int h   = lane >> 2;
    const int sm4 = lane & 3;

    // stage src indices + edge_attr (coalesced)
    s_src[warp][lane] = src_idx[(size_t)q * KNN + lane];
    {
        const float4* ea4 = (const float4*)(edge_attr + (size_t)q * KNN * E_F);
#pragma unroll
        for (int t = 0; t < 4; t++)
            s_ea[warp][lane + 32 * t] = ea4[lane + 32 * t];
    }

    // full Q head h (16 floats) and W_rbf row h (16 floats)
    float qv[16], wr[16];
    {
        const float4* qp = (const float4*)(Qq + (size_t)q * HID + h * 16);
        const float4* wp = (const float4*)(W_rbf + h * E_F);
#pragma unroll
        for (int i = 0; i < 4; i++) {
            float4 a = qp[i];
            qv[i * 4 + 0] = a.x; qv[i * 4 + 1] = a.y;
            qv[i * 4 + 2] = a.z; qv[i * 4 + 3] = a.w;
            float4 b = wp[i];
            wr[i * 4 + 0] = b.x; wr[i * 4 + 1] = b.y;
            wr[i * 4 + 2] = b.z; wr[i * 4 + 3] = b.w;
        }
    }
    __syncwarp();

    // scores for my 8 edges, no shuffles
    float sc[8];
#pragma unroll
    for (int t = 0; t < 8; t++) {
        const int j  = sm4 + 4 * t;
        const int sj = s_src[warp][j];
        const uint4 k0 = *(const uint4*)(Ka + (size_t)sj * HID + h * 16);
        const uint4 k1 = *(const uint4*)(Ka + (size_t)sj * HID + h * 16 + 8);
        float dd = 0.f;
        {
            const __half2* kh = (const __half2*)&k0;
#pragma unroll
            for (int i = 0; i < 4; i++) {
                const float2 f = __half22float2(kh[i]);
                dd = fmaf(qv[i * 2 + 0], f.x, dd);
                dd = fmaf(qv[i * 2 + 1], f.y, dd);
            }
            const __half2* kh1 = (const __half2*)&k1;
#pragma unroll
            for (int i = 0; i < 4; i++) {
                const float2 f = __half22float2(kh1[i]);
                dd = fmaf(qv[8 + i * 2 + 0], f.x, dd);
                dd = fmaf(qv[8 + i * 2 + 1], f.y, dd);
            }
        }
        float rr = 0.f;
#pragma unroll
        for (int c = 0; c < 4; c++) {
            const float4 e = s_ea[warp][j * 4 + c];
            rr = fmaf(e.x, wr[c * 4 + 0], rr);
            rr = fmaf(e.y, wr[c * 4 + 1], rr);
            rr = fmaf(e.z, wr[c * 4 + 2], rr);
            rr = fmaf(e.w, wr[c * 4 + 3], rr);
        }
        sc[t] = dd * 0.25f + rr;
    }

    // softmax over the head's 32 edges (in-lane 8 + cross-sm4 shfls)
    float m = sc[0];
#pragma unroll
    for (int t = 1; t < 8; t++) m = fmaxf(m, sc[t]);
    m = fmaxf(m, __shfl_xor_sync(0xffffffffu, m, 1));
    m = fmaxf(m, __shfl_xor_sync(0xffffffffu, m, 2));
    float sum = 0.f;
#pragma unroll
    for (int t = 0; t < 8; t++) { sc[t] = __expf(sc[t] - m); sum += sc[t]; }
    sum += __shfl_xor_sync(0xffffffffu, sum, 1);
    sum += __shfl_xor_sync(0xffffffffu, sum, 2);
    const float inv = 1.f / (sum + 1e-16f);
#pragma unroll
    for (int t = 0; t < 8; t++)
        s_al[warp][h * 36 + sm4 + 4 * t] = sc[t] * inv;
    __syncwarp();

    // weighted V aggregation: lane covers dims [4*lane, 4*lane+4)
    float4 acc = make_float4(0.f, 0.f, 0.f, 0.f);
#pragma unroll
    for (int j = 0; j < KNN; j++) {
        const float a  = s_al[warp][h * 36 + j];
        const int   sj = s_src[warp][j];
        const __half2* vr = (const __half2*)(Va + (size_t)sj * HID);
        const float2 v01 = __half22float2(vr[lane * 2 + 0]);
        const float2 v23 = __half22float2(vr[lane * 2 + 1]);
        acc.x = fmaf(a, v01.x, acc.x);
        acc.y = fmaf(a, v01.y, acc.y);
        acc.z = fmaf(a, v23.x, acc.z);
        acc.w = fmaf(a, v23.y, acc.w);
    }
    *(float4*)&agg[(size_t)q * HID + lane * 4] = acc;
}

// ---------------------------------------------------------------------------
extern "C" void kernel_launch(void* const* d_in, const int* in_sizes, int n_in,
                              void* d_out, int out_size)
{
    const float* h_atom    = (const float*)d_in[0];
    const float* h_query   = (const float*)d_in[1];
    const float* edge_attr = (const float*)d_in[2];
    const float* W_q       = (const float*)d_in[3];
    const float* W_k       = (const float*)d_in[4];
    const float* W_v       = (const float*)d_in[5];
    const float* W_rbf     = (const float*)d_in[6];
    const float* W1        = (const float*)d_in[7];
    const float* b1        = (const float*)d_in[8];
    const float* W2        = (const float*)d_in[9];
    const float* b2        = (const float*)d_in[10];
    const float* ln_gamma  = (const float*)d_in[11];
    const float* ln_beta   = (const float*)d_in[12];
    const int*   edge_index= (const int*)  d_in[13];   // [2,E]; row0 = src
    float* out = (float*)d_out;

    float *Qq, *agg;
    __half *Ka, *Va;
    cudaGetSymbolAddress((void**)&Qq,  g_Qq);
    cudaGetSymbolAddress((void**)&Ka,  g_Ka);
    cudaGetSymbolAddress((void**)&Va,  g_Va);
    cudaGetSymbolAddress((void**)&agg, g_agg);

    cudaFuncSetAttribute(proj_all,
                         cudaFuncAttributeMaxDynamicSharedMemorySize, 98304);
    cudaFuncSetAttribute(mlp_fused,
                         cudaFuncAttributeMaxDynamicSharedMemorySize, 98304);

    // persistent Q+K+V projections (weights packed once; decoupled quad-groups)
    proj_all<<<KVC + QC, 512, 98304>>>(h_atom, h_query, W_k, W_v, W_q,
                                       Ka, Va, Qq);

    // segment-softmax attention + aggregation (shuffle-free score phase)
    attn_kernel<<<NQ / 8, 256>>>(Qq, Ka, Va, edge_attr, edge_index, W_rbf, agg);

    // fused MLP1 + ReLU + MLP2 + residual + LayerNorm
    mlp_fused<<<MLPB, 512, 98304>>>(h_query, agg, W1, b1, W2, b2,
                                    ln_gamma, ln_beta, out);
}